// round 16
// baseline (speedup 1.0000x reference)
#include <cuda_runtime.h>
#include <cuda_bf16.h>
#include <cstdint>
#include <math.h>

#define DM    512
#define DFF   2048
#define BATCH 4
#define LSEQ  2048
#define MTOK  (BATCH * LSEQ)   // 8192 rows
#define NH    8
#define DK    64
#define EPSLN 1e-5f
#define QKVS  1536             // fused qkv logical width
#define QKS   1024             // q|k buffer row stride (fp32)

// ---------------------------------------------------------------------------
// Scratch (device globals)
// ---------------------------------------------------------------------------
__device__ __nv_bfloat16 g_hb  [(size_t)MTOK * DM];      // LN outputs (bf16)
__device__ float         g_qk  [(size_t)MTOK * QKS];     // q|k (rna-fp32)
__device__ __nv_bfloat16 g_vb  [(size_t)MTOK * DM];      // v (bf16)
__device__ __nv_bfloat16 g_attb[(size_t)MTOK * DM];      // attention out (bf16)
__device__ __nv_bfloat16 g_ffb [(size_t)MTOK * DFF];     // gelu out (bf16)
__device__ __nv_bfloat16 g_wtb [1536*512 + 512*512 + 512*2048 + 512*2048];
__device__ float         g_bqkv[QKVS];

#define WT_O  (1536*512)
#define WT_1  (WT_O + 512*512)
#define WT_2  (WT_1 + 512*2048)

// ---------------------------------------------------------------------------
// PTX helpers (baseline PTX only)
// ---------------------------------------------------------------------------
__device__ __forceinline__ uint32_t smem_u32(const void* p) {
    uint32_t a;
    asm("{ .reg .u64 t; cvta.to.shared.u64 t, %1; cvt.u32.u64 %0, t; }" : "=r"(a) : "l"(p));
    return a;
}
__device__ __forceinline__ float f_rna_tf32(float x) {
    uint32_t u;
    asm("cvt.rna.tf32.f32 %0, %1;" : "=r"(u) : "f"(x));
    return __uint_as_float(u);
}
__device__ __forceinline__ uint32_t pk_bf16(float lo, float hi) {
    __nv_bfloat162 h = __floats2bfloat162_rn(lo, hi);
    return *reinterpret_cast<uint32_t*>(&h);
}

#define CP_ASYNC16(dst, src) \
    asm volatile("cp.async.cg.shared.global [%0], [%1], 16;" :: "r"(dst), "l"(src))
#define CP_COMMIT() asm volatile("cp.async.commit_group;" ::: "memory")
#define CP_WAIT1()  asm volatile("cp.async.wait_group 1;" ::: "memory")

#define LDSM4(r0, r1, r2, r3, addr) \
    asm volatile("ldmatrix.sync.aligned.m8n8.x4.shared.b16 {%0,%1,%2,%3}, [%4];" \
        : "=r"(r0), "=r"(r1), "=r"(r2), "=r"(r3) : "r"(addr))

#define LDSM4T(r0, r1, r2, r3, addr) \
    asm volatile("ldmatrix.sync.aligned.m8n8.x4.trans.shared.b16 {%0,%1,%2,%3}, [%4];" \
        : "=r"(r0), "=r"(r1), "=r"(r2), "=r"(r3) : "r"(addr))

__device__ __forceinline__ void mma_tf32(
    float& d0, float& d1, float& d2, float& d3,
    uint32_t a0, uint32_t a1, uint32_t a2, uint32_t a3,
    uint32_t b0, uint32_t b1)
{
    asm volatile(
        "mma.sync.aligned.m16n8k8.row.col.f32.tf32.tf32.f32 "
        "{%0,%1,%2,%3}, {%4,%5,%6,%7}, {%8,%9}, {%0,%1,%2,%3};"
        : "+f"(d0), "+f"(d1), "+f"(d2), "+f"(d3)
        : "r"(a0), "r"(a1), "r"(a2), "r"(a3), "r"(b0), "r"(b1));
}

__device__ __forceinline__ void mma_bf16(
    float& d0, float& d1, float& d2, float& d3,
    uint32_t a0, uint32_t a1, uint32_t a2, uint32_t a3,
    uint32_t b0, uint32_t b1)
{
    asm volatile(
        "mma.sync.aligned.m16n8k16.row.col.f32.bf16.bf16.f32 "
        "{%0,%1,%2,%3}, {%4,%5,%6,%7}, {%8,%9}, {%0,%1,%2,%3};"
        : "+f"(d0), "+f"(d1), "+f"(d2), "+f"(d3)
        : "r"(a0), "r"(a1), "r"(a2), "r"(a3), "r"(b0), "r"(b1));
}

__device__ __forceinline__ float gelu_exact(float x) {
    return 0.5f * x * (1.0f + erff(x * 0.70710678118654752440f));
}

// exp(x), x<=0, FMA-pipe polynomial (avoids MUFU wall)
__device__ __forceinline__ float exp_fast(float x) {
    float z = x * 1.44269504088896341f;
    z = fmaxf(z, -126.0f);
    float n = floorf(z);
    float f = z - n;
    float p = fmaf(f, 1.54035304e-4f, 0.00133335581f);
    p = fmaf(f, p, 0.00961812911f);
    p = fmaf(f, p, 0.0555041087f);
    p = fmaf(f, p, 0.2402265070f);
    p = fmaf(f, p, 0.69314718056f);
    p = fmaf(f, p, 1.0f);
    return p * __int_as_float(((int)n + 127) << 23);
}

// ---------------------------------------------------------------------------
// LayerNorm: 2 rows per block, 128 threads/row, float4 path; writes bf16
// ---------------------------------------------------------------------------
__global__ __launch_bounds__(256) void layernorm_kernel(
    const float* __restrict__ x, const float* __restrict__ g,
    const float* __restrict__ be, __nv_bfloat16* __restrict__ out)
{
    __shared__ float red[2][4];
    int tid = threadIdx.x;
    int r = tid >> 7;
    int t = tid & 127;
    int wq = (tid >> 5) & 3;
    int row = blockIdx.x * 2 + r;

    float4 v = *reinterpret_cast<const float4*>(x + (size_t)row * DM + t * 4);

    float s = v.x + v.y + v.z + v.w;
    #pragma unroll
    for (int o = 16; o; o >>= 1) s += __shfl_xor_sync(0xffffffffu, s, o);
    if ((tid & 31) == 0) red[r][wq] = s;
    __syncthreads();
    float mu = (red[r][0] + red[r][1] + red[r][2] + red[r][3]) * (1.0f / DM);
    __syncthreads();

    float4 d;
    d.x = v.x - mu; d.y = v.y - mu; d.z = v.z - mu; d.w = v.w - mu;
    s = d.x * d.x + d.y * d.y + d.z * d.z + d.w * d.w;
    #pragma unroll
    for (int o = 16; o; o >>= 1) s += __shfl_xor_sync(0xffffffffu, s, o);
    if ((tid & 31) == 0) red[r][wq] = s;
    __syncthreads();
    float rs = rsqrtf((red[r][0] + red[r][1] + red[r][2] + red[r][3]) * (1.0f / DM)
                      + EPSLN);

    float4 gv = *reinterpret_cast<const float4*>(g + t * 4);
    float4 bv = *reinterpret_cast<const float4*>(be + t * 4);
    uint2 o2;
    o2.x = pk_bf16(d.x * rs * gv.x + bv.x, d.y * rs * gv.y + bv.y);
    o2.y = pk_bf16(d.z * rs * gv.z + bv.z, d.w * rs * gv.w + bv.w);
    *reinterpret_cast<uint2*>(out + (size_t)row * DM + t * 4) = o2;
}

// ---------------------------------------------------------------------------
// All 6 weight transposes (fp32 [R][C] -> bf16 [C][R]) in ONE kernel.
// ---------------------------------------------------------------------------
__global__ __launch_bounds__(256) void transpose_all_kernel(
    const float* __restrict__ Wq, const float* __restrict__ Wk,
    const float* __restrict__ Wv, const float* __restrict__ Wo,
    const float* __restrict__ W1, const float* __restrict__ W2,
    __nv_bfloat16* __restrict__ wtb)
{
    __shared__ float t[32][33];
    int bid = blockIdx.x;
    const float* in;
    __nv_bfloat16* out;
    int R, C, lb;
    if (bid < 256)        { in = Wq; out = wtb;              R = 512;  C = 512;  lb = bid; }
    else if (bid < 512)   { in = Wk; out = wtb + 512 * 512;  R = 512;  C = 512;  lb = bid - 256; }
    else if (bid < 768)   { in = Wv; out = wtb + 1024 * 512; R = 512;  C = 512;  lb = bid - 512; }
    else if (bid < 1024)  { in = Wo; out = wtb + WT_O;       R = 512;  C = 512;  lb = bid - 768; }
    else if (bid < 2048)  { in = W1; out = wtb + WT_1;       R = 512;  C = 2048; lb = bid - 1024; }
    else                  { in = W2; out = wtb + WT_2;       R = 2048; C = 512;  lb = bid - 2048; }
    int nbx = C >> 5;
    int bx = (lb % nbx) << 5;
    int by = (lb / nbx) << 5;
    int txl = threadIdx.x, tyl = threadIdx.y;
    #pragma unroll
    for (int i = 0; i < 32; i += 8)
        t[tyl + i][txl] = in[(size_t)(by + tyl + i) * C + bx + txl];
    __syncthreads();
    #pragma unroll
    for (int i = 0; i < 32; i += 8)
        out[(size_t)(bx + tyl + i) * R + by + txl] =
            __float2bfloat16_rn(t[txl][tyl + i]);
}

__global__ void concat_bias_kernel(
    const float* __restrict__ bq, const float* __restrict__ bk,
    const float* __restrict__ bv, float* __restrict__ o)
{
    int i = blockIdx.x * 256 + threadIdx.x;
    if (i < QKVS)
        o[i] = i < 512 ? bq[i] : (i < 1024 ? bk[i - 512] : bv[i - 1024]);
}

// ---------------------------------------------------------------------------
// bf16 tensor-core GEMM (R13 config, frozen), mode 3 = fused-QKV split out:
// Q|K cols (<1024) as rna-fp32 (stride 1024) into Cv; V cols as bf16 into res.
// ---------------------------------------------------------------------------
#define GP    36                  // smem row pitch in u32 (= 72 bf16, 144B)
#define OSTG  (128 * GP)          // per operand per stage (u32)
#define STG   (2 * OSTG)          // per stage (u32)
#define SMEM_GEMM (2 * STG * 4)   // 73728 bytes

__global__ __launch_bounds__(256, 2) void gemm_bf16_kernel(
    const __nv_bfloat16* __restrict__ A, const __nv_bfloat16* __restrict__ BT,
    const float* __restrict__ bias, const float* __restrict__ res,
    void* __restrict__ Cv, int M, int N, int K, int mode)
{
    extern __shared__ float smem[];
    const uint32_t sb = smem_u32(smem);
    const int tid = threadIdx.x;
    const int wid = tid >> 5;
    const int lid = tid & 31;
    const int g = lid >> 2;
    const int t = lid & 3;
    const int bm = blockIdx.y * 128;
    const int bn = blockIdx.x * 128;
    const int m_off = (wid & 1) * 64;
    const int n_off = (wid >> 1) * 32;
    const int nchunk = K >> 6;

    const int lr  = lid & 7;
    const int lt3 = lid >> 3;
    const uint32_t aRow  = m_off + (lt3 & 1) * 8 + lr;
    const uint32_t aKoff = (uint32_t)(lt3 >> 1) * 4;
    const uint32_t bRow  = n_off + (lt3 >> 1) * 8 + lr;
    const uint32_t bKoff = (uint32_t)(lt3 & 1) * 4;

    float acc[4][4][4];
    #pragma unroll
    for (int mf = 0; mf < 4; mf++)
        #pragma unroll
        for (int nf = 0; nf < 4; nf++)
            #pragma unroll
            for (int r = 0; r < 4; r++) acc[mf][nf][r] = 0.f;

    auto issue = [&](int c, int s) {
        const int k0 = c << 6;
        const uint32_t sbase = sb + (uint32_t)(s * STG) * 4u;
        #pragma unroll
        for (int it = 0; it < 8; it++) {
            int u = it * 256 + tid;
            int op = u >> 10;
            int v = u & 1023;
            int row = v >> 3;
            int c8 = v & 7;
            const __nv_bfloat16* src = op
                ? (BT + (size_t)(bn + row) * K + k0 + (c8 << 3))
                : (A  + (size_t)(bm + row) * K + k0 + (c8 << 3));
            uint32_t dst = sbase +
                (uint32_t)(op * OSTG + row * GP + (c8 << 2)) * 4u;
            CP_ASYNC16(dst, src);
        }
    };

    issue(0, 0);
    CP_COMMIT();

    int buf = 0;
    for (int c = 0; c < nchunk; c++) {
        if (c + 1 < nchunk) issue(c + 1, buf ^ 1);
        CP_COMMIT();
        CP_WAIT1();
        __syncthreads();

        const uint32_t sA = sb + (uint32_t)(buf * STG) * 4u;
        const uint32_t sB = sA + (uint32_t)OSTG * 4u;

        #pragma unroll
        for (int ks = 0; ks < 4; ks++) {
            const uint32_t kb = ks * 8;
            uint32_t b01[4], b23[4];
            LDSM4(b01[0], b01[1], b01[2], b01[3],
                  sB + ((bRow +  0) * GP + kb + bKoff) * 4u);
            LDSM4(b23[0], b23[1], b23[2], b23[3],
                  sB + ((bRow + 16) * GP + kb + bKoff) * 4u);
            uint32_t aC[4], aN[4];
            LDSM4(aC[0], aC[1], aC[2], aC[3],
                  sA + ((aRow + 0 * 16) * GP + kb + aKoff) * 4u);
            #pragma unroll
            for (int mf = 0; mf < 4; mf++) {
                if (mf < 3)
                    LDSM4(aN[0], aN[1], aN[2], aN[3],
                          sA + ((aRow + (mf + 1) * 16) * GP + kb + aKoff) * 4u);
                mma_bf16(acc[mf][0][0], acc[mf][0][1], acc[mf][0][2], acc[mf][0][3],
                         aC[0], aC[1], aC[2], aC[3], b01[0], b01[1]);
                mma_bf16(acc[mf][1][0], acc[mf][1][1], acc[mf][1][2], acc[mf][1][3],
                         aC[0], aC[1], aC[2], aC[3], b01[2], b01[3]);
                mma_bf16(acc[mf][2][0], acc[mf][2][1], acc[mf][2][2], acc[mf][2][3],
                         aC[0], aC[1], aC[2], aC[3], b23[0], b23[1]);
                mma_bf16(acc[mf][3][0], acc[mf][3][1], acc[mf][3][2], acc[mf][3][3],
                         aC[0], aC[1], aC[2], aC[3], b23[2], b23[3]);
                #pragma unroll
                for (int r = 0; r < 4; r++) aC[r] = aN[r];
            }
        }
        __syncthreads();
        buf ^= 1;
    }

    // ---- epilogue ----
    const bool isV = (mode == 3) && (bn >= 1024);   // uniform per CTA
    #pragma unroll
    for (int nf = 0; nf < 4; nf++) {
        int col = bn + n_off + nf * 8 + 2 * t;
        float2 bi = *reinterpret_cast<const float2*>(bias + col);
        #pragma unroll
        for (int mf = 0; mf < 4; mf++) {
            int r0 = bm + m_off + mf * 16 + g;
            #pragma unroll
            for (int half = 0; half < 2; half++) {
                int r = r0 + half * 8;
                float v0 = acc[mf][nf][half * 2 + 0] + bi.x;
                float v1 = acc[mf][nf][half * 2 + 1] + bi.y;
                if (mode == 1) {
                    __nv_bfloat162 o2 = __floats2bfloat162_rn(
                        gelu_exact(v0), gelu_exact(v1));
                    *reinterpret_cast<__nv_bfloat162*>(
                        (__nv_bfloat16*)Cv + (size_t)r * N + col) = o2;
                } else if (mode == 3) {
                    if (isV) {
                        __nv_bfloat162 o2 = __floats2bfloat162_rn(v0, v1);
                        *reinterpret_cast<__nv_bfloat162*>(
                            (__nv_bfloat16*)res + (size_t)r * DM + (col - 1024)) = o2;
                    } else {
                        float2 o;
                        o.x = f_rna_tf32(v0);
                        o.y = f_rna_tf32(v1);
                        *reinterpret_cast<float2*>(
                            (float*)Cv + (size_t)r * QKS + col) = o;
                    }
                } else {
                    if (mode == 2) {
                        float2 rv = *reinterpret_cast<const float2*>(
                            res + (size_t)r * N + col);
                        v0 += rv.x; v1 += rv.y;
                    }
                    float2 o; o.x = v0; o.y = v1;
                    *reinterpret_cast<float2*>(
                        (float*)Cv + (size_t)r * N + col) = o;
                }
            }
        }
    }
}

// ---------------------------------------------------------------------------
// Tensor-core causal flash attention with DOUBLE-BUFFERED cp.async K/V.
// Operands pre-converted by QKV GEMM: Q,K rna-fp32 (stride 1024), V bf16.
// QK^T tf32 via ldmatrix; PV bf16 via trans-ldmatrix; P register-direct.
// CTA = 128 queries x (b,h); 8 warps x 16 rows; occ 2 (92.4KB smem/CTA).
// ---------------------------------------------------------------------------
#define QS_PAD 68
#define KS_PAD 76
#define VBP    72                              // V bf16 pitch (bf16 units)
#define QS_OFF 0
#define MK_OFF (128 * QS_PAD)                  // 8704 (floats)
#define ST_OFF (MK_OFF + 64)                   // 8768
#define KSTF   (64 * KS_PAD)                   // 4864 floats per stage K
#define VSTF   (64 * (VBP / 2))                // 2304 floats per stage V
#define STAGEF (KSTF + VSTF)                   // 7168 floats per stage
#define SMEM_ATTN ((ST_OFF + 2 * STAGEF) * 4)  // 92416 bytes

__global__ __launch_bounds__(256, 2) void attn_tc_kernel(
    const float* __restrict__ QK, const __nv_bfloat16* __restrict__ VB,
    const int* __restrict__ mask, __nv_bfloat16* __restrict__ O)
{
    extern __shared__ float sm[];
    float* Qs = sm + QS_OFF;
    int*   mk = (int*)(sm + MK_OFF);
    const uint32_t sb = smem_u32(sm);

    const int qt = (int)gridDim.x - 1 - (int)blockIdx.x;
    const int h = blockIdx.y, b = blockIdx.z;
    const int q0 = qt * 128;
    const int tid = threadIdx.x;
    const int w = tid >> 5;
    const int lid = tid & 31;
    const int g = lid >> 2;
    const int t = lid & 3;
    const size_t baseQ = (size_t)b * LSEQ * QKS + (size_t)h * DK;
    const size_t baseK = baseQ + DM;
    const size_t baseV = (size_t)b * LSEQ * DM + (size_t)h * DK;
    const size_t baseO = baseV;

    const int lr  = lid & 7;
    const int sub = lid >> 3;
    const uint32_t qOff = (uint32_t)(lid & 15) * QS_PAD + (uint32_t)(lid >> 4) * 4;
    const uint32_t kOff = ((uint32_t)lr + (uint32_t)(sub & 2) * 4) * KS_PAD
                        + (uint32_t)(sub & 1) * 4;
    const uint32_t vRowOff = (uint32_t)((sub & 1) * 8 + lr) * VBP;
    const uint32_t vColOff = (uint32_t)(sub >> 1) * 8;

    const int nkb = 2 * qt + 2;

    // cp.async K/V stage loader (pure copy; operands pre-converted)
    auto issueKV = [&](int kb2, int s) {
        const int k0 = kb2 * 64;
        const uint32_t stK = sb + (uint32_t)(ST_OFF + s * STAGEF) * 4u;
        const uint32_t stV = stK + (uint32_t)KSTF * 4u;
        #pragma unroll
        for (int it = 0; it < 4; it++) {      // K: 64x64 fp32, 1024 x 16B
            int u = it * 256 + tid;
            int r = u >> 4;
            int c4 = (u & 15) << 2;
            CP_ASYNC16(stK + (uint32_t)(r * KS_PAD + c4) * 4u,
                       QK + baseK + (size_t)(k0 + r) * QKS + c4);
        }
        #pragma unroll
        for (int it = 0; it < 2; it++) {      // V: 64x64 bf16, 512 x 16B
            int u = it * 256 + tid;
            int r = u >> 3;
            int c8 = (u & 7) << 3;
            CP_ASYNC16(stV + (uint32_t)(r * VBP + c8) * 2u,
                       VB + baseV + (size_t)(k0 + r) * DM + c8);
        }
    };

    // prologue: kick off block 0 loads, then stage Q
    issueKV(0, 0);
    CP_COMMIT();
    #pragma unroll
    for (int it = 0; it < 8; it++) {
        int li = it * 256 + tid;
        int r = li >> 4;
        int c = (li & 15) << 2;
        *reinterpret_cast<float4*>(Qs + r * QS_PAD + c) =
            *reinterpret_cast<const float4*>(
                QK + baseQ + (size_t)(q0 + r) * QKS + c);
    }

    float acc[8][4];
    #pragma unroll
    for (int nf = 0; nf < 8; nf++)
        #pragma unroll
        for (int r = 0; r < 4; r++) acc[nf][r] = 0.f;
    float m_lo = -1e30f, m_hi = -1e30f, l_lo = 0.f, l_hi = 0.f;

    const int row_lo = q0 + w * 16 + g;
    const int row_hi = row_lo + 8;
    const uint32_t sQw = sb + (uint32_t)(w * 16 * QS_PAD) * 4u;

    int buf = 0;
    for (int kb = 0; kb < nkb; kb++) {
        const int k0 = kb * 64;
        if (kb + 1 < nkb) issueKV(kb + 1, buf ^ 1);
        CP_COMMIT();
        CP_WAIT1();                 // committed = kb+2; <=1 pending pins block kb
        if (tid < 64) mk[tid] = mask[b * LSEQ + k0 + tid];
        __syncthreads();            // cp.async data + mk (+ Q on kb==0) visible

        const uint32_t sKs = sb + (uint32_t)(ST_OFF + buf * STAGEF) * 4u;
        const uint32_t sVb = sKs + (uint32_t)KSTF * 4u;

        // ---- S = Q K^T (tf32, ldmatrix fragments) ----
        float s[8][4];
        #pragma unroll
        for (int nf = 0; nf < 8; nf++)
            #pragma unroll
            for (int r = 0; r < 4; r++) s[nf][r] = 0.f;

        #pragma unroll
        for (int ks = 0; ks < 8; ks++) {
            const uint32_t ko = ks * 8;
            uint32_t qa0, qa1, qa2, qa3;
            LDSM4(qa0, qa1, qa2, qa3, sQw + (qOff + ko) * 4u);
            #pragma unroll
            for (int np = 0; np < 4; np++) {
                uint32_t k0r, k1r, k2r, k3r;
                LDSM4(k0r, k1r, k2r, k3r,
                      sKs + ((uint32_t)(np * 16) * KS_PAD + kOff + ko) * 4u);
                mma_tf32(s[2*np  ][0], s[2*np  ][1], s[2*np  ][2], s[2*np  ][3],
                         qa0, qa1, qa2, qa3, k0r, k1r);
                mma_tf32(s[2*np+1][0], s[2*np+1][1], s[2*np+1][2], s[2*np+1][3],
                         qa0, qa1, qa2, qa3, k2r, k3r);
            }
        }

        // ---- scale + causal + pad mask ----
        #pragma unroll
        for (int nf = 0; nf < 8; nf++) {
            int cl = nf * 8 + 2 * t;
            int key0 = k0 + cl;
            int key1 = key0 + 1;
            int m0 = mk[cl];
            int m1 = mk[cl + 1];
            s[nf][0] = (key0 > row_lo || m0 == 0) ? -1e9f : s[nf][0] * 0.125f;
            s[nf][1] = (key1 > row_lo || m1 == 0) ? -1e9f : s[nf][1] * 0.125f;
            s[nf][2] = (key0 > row_hi || m0 == 0) ? -1e9f : s[nf][2] * 0.125f;
            s[nf][3] = (key1 > row_hi || m1 == 0) ? -1e9f : s[nf][3] * 0.125f;
        }

        // ---- online softmax ----
        float bm_lo = s[0][0], bm_hi = s[0][2];
        #pragma unroll
        for (int nf = 0; nf < 8; nf++) {
            bm_lo = fmaxf(bm_lo, fmaxf(s[nf][0], s[nf][1]));
            bm_hi = fmaxf(bm_hi, fmaxf(s[nf][2], s[nf][3]));
        }
        bm_lo = fmaxf(bm_lo, __shfl_xor_sync(0xffffffffu, bm_lo, 1));
        bm_lo = fmaxf(bm_lo, __shfl_xor_sync(0xffffffffu, bm_lo, 2));
        bm_hi = fmaxf(bm_hi, __shfl_xor_sync(0xffffffffu, bm_hi, 1));
        bm_hi = fmaxf(bm_hi, __shfl_xor_sync(0xffffffffu, bm_hi, 2));

        float mn_lo = fmaxf(m_lo, bm_lo);
        float mn_hi = fmaxf(m_hi, bm_hi);
        float co_lo = exp_fast(m_lo - mn_lo);
        float co_hi = exp_fast(m_hi - mn_hi);

        float sum_lo = 0.f, sum_hi = 0.f;
        #pragma unroll
        for (int nf = 0; nf < 8; nf++) {
            s[nf][0] = exp_fast(s[nf][0] - mn_lo);
            s[nf][1] = exp_fast(s[nf][1] - mn_lo);
            s[nf][2] = exp_fast(s[nf][2] - mn_hi);
            s[nf][3] = exp_fast(s[nf][3] - mn_hi);
            sum_lo += s[nf][0] + s[nf][1];
            sum_hi += s[nf][2] + s[nf][3];
        }
        sum_lo += __shfl_xor_sync(0xffffffffu, sum_lo, 1);
        sum_lo += __shfl_xor_sync(0xffffffffu, sum_lo, 2);
        sum_hi += __shfl_xor_sync(0xffffffffu, sum_hi, 1);
        sum_hi += __shfl_xor_sync(0xffffffffu, sum_hi, 2);

        l_lo = l_lo * co_lo + sum_lo;
        l_hi = l_hi * co_hi + sum_hi;
        m_lo = mn_lo; m_hi = mn_hi;
        #pragma unroll
        for (int nf = 0; nf < 8; nf++) {
            acc[nf][0] *= co_lo; acc[nf][1] *= co_lo;
            acc[nf][2] *= co_hi; acc[nf][3] *= co_hi;
        }

        // ---- acc += P V (bf16; P from registers, V via trans-ldmatrix) ----
        #pragma unroll
        for (int ks = 0; ks < 4; ks++) {
            uint32_t a0 = pk_bf16(s[2 * ks    ][0], s[2 * ks    ][1]);
            uint32_t a1 = pk_bf16(s[2 * ks    ][2], s[2 * ks    ][3]);
            uint32_t a2 = pk_bf16(s[2 * ks + 1][0], s[2 * ks + 1][1]);
            uint32_t a3 = pk_bf16(s[2 * ks + 1][2], s[2 * ks + 1][3]);
            const uint32_t vk = (uint32_t)(ks * 16) * VBP;
            #pragma unroll
            for (int np = 0; np < 4; np++) {
                uint32_t b0, b1, b2, b3;
                LDSM4T(b0, b1, b2, b3,
                       sVb + (vk + vRowOff + (uint32_t)(np * 16) + vColOff) * 2u);
                mma_bf16(acc[2*np  ][0], acc[2*np  ][1], acc[2*np  ][2], acc[2*np  ][3],
                         a0, a1, a2, a3, b0, b1);
                mma_bf16(acc[2*np+1][0], acc[2*np+1][1], acc[2*np+1][2], acc[2*np+1][3],
                         a0, a1, a2, a3, b2, b3);
            }
        }
        __syncthreads();            // all warps done reading stage buf
        buf ^= 1;
    }

    float inv_lo = 1.0f / l_lo;
    float inv_hi = 1.0f / l_hi;
    #pragma unroll
    for (int nf = 0; nf < 8; nf++) {
        int cl = nf * 8 + 2 * t;
        __nv_bfloat162 o2;
        o2 = __floats2bfloat162_rn(acc[nf][0] * inv_lo, acc[nf][1] * inv_lo);
        *reinterpret_cast<__nv_bfloat162*>(
            O + baseO + (size_t)row_lo * DM + cl) = o2;
        o2 = __floats2bfloat162_rn(acc[nf][2] * inv_hi, acc[nf][3] * inv_hi);
        *reinterpret_cast<__nv_bfloat162*>(
            O + baseO + (size_t)row_hi * DM + cl) = o2;
    }
}

// ---------------------------------------------------------------------------
// Launch
// ---------------------------------------------------------------------------
extern "C" void kernel_launch(void* const* d_in, const int* in_sizes, int n_in,
                              void* d_out, int out_size)
{
    const float* x    = (const float*)d_in[0];
    const int*   mask = (const int*)  d_in[1];
    const float* Wq   = (const float*)d_in[2];
    const float* bq   = (const float*)d_in[3];
    const float* Wk   = (const float*)d_in[4];
    const float* bk   = (const float*)d_in[5];
    const float* Wv   = (const float*)d_in[6];
    const float* bv   = (const float*)d_in[7];
    const float* Wo   = (const float*)d_in[8];
    const float* bo   = (const float*)d_in[9];
    const float* g1   = (const float*)d_in[10];
    const float* be1  = (const float*)d_in[11];
    const float* g2   = (const float*)d_in[12];
    const float* be2  = (const float*)d_in[13];
    const float* W1   = (const float*)d_in[14];
    const float* b1   = (const float*)d_in[15];
    const float* W2   = (const float*)d_in[16];
    const float* b2   = (const float*)d_in[17];
    float* out = (float*)d_out;

    __nv_bfloat16 *hb, *vb, *attb, *ffb, *wtb;
    float *qk, *bqkv;
    cudaGetSymbolAddress((void**)&hb,   g_hb);
    cudaGetSymbolAddress((void**)&qk,   g_qk);
    cudaGetSymbolAddress((void**)&vb,   g_vb);
    cudaGetSymbolAddress((void**)&attb, g_attb);
    cudaGetSymbolAddress((void**)&ffb,  g_ffb);
    cudaGetSymbolAddress((void**)&wtb,  g_wtb);
    cudaGetSymbolAddress((void**)&bqkv, g_bqkv);

    cudaFuncSetAttribute(gemm_bf16_kernel,
        cudaFuncAttributeMaxDynamicSharedMemorySize, SMEM_GEMM);
    cudaFuncSetAttribute(attn_tc_kernel,
        cudaFuncAttributeMaxDynamicSharedMemorySize, SMEM_ATTN);

    // 0. all weight transposes in one launch + bias concat
    transpose_all_kernel<<<3072, dim3(32, 8)>>>(Wq, Wk, Wv, Wo, W1, W2, wtb);
    concat_bias_kernel<<<6, 256>>>(bq, bk, bv, bqkv);

    // 1. ln1(x) -> hb
    layernorm_kernel<<<MTOK / 2, 256>>>(x, g1, be1, hb);

    // 2. fused QKV projection: Q|K -> qk (rna-fp32), V -> vb (bf16)
    gemm_bf16_kernel<<<dim3(QKVS / 128, MTOK / 128), 256, SMEM_GEMM>>>(
        hb, wtb, bqkv, (const float*)vb, qk, MTOK, QKVS, DM, 3);

    // 3. causal attention -> attb (bf16)
    dim3 gattn(LSEQ / 128, NH, BATCH);
    attn_tc_kernel<<<gattn, 256, SMEM_ATTN>>>(qk, vb, mask, attb);

    // 4. O projection + residual(x) -> out
    gemm_bf16_kernel<<<dim3(DM / 128, MTOK / 128), 256, SMEM_GEMM>>>(
        attb, wtb + WT_O, bo, x, out, MTOK, DM, DM, 2);

    // 5. ln2(out) -> hb
    layernorm_kernel<<<MTOK / 2, 256>>>(out, g2, be2, hb);

    // 6. FFN1 + GELU -> ffb (bf16)
    gemm_bf16_kernel<<<dim3(DFF / 128, MTOK / 128), 256, SMEM_GEMM>>>(
        hb, wtb + WT_1, b1, nullptr, ffb, MTOK, DFF, DM, 1);

    // 7. FFN2 + residual -> out
    gemm_bf16_kernel<<<dim3(DM / 128, MTOK / 128), 256, SMEM_GEMM>>>(
        ffb, wtb + WT_2, b2, out, out, MTOK, DM, DFF, 2);
}

// round 17
// speedup vs baseline: 1.5358x; 1.5358x over previous
#include <cuda_runtime.h>
#include <cuda_bf16.h>
#include <cstdint>
#include <math.h>

#define DM    512
#define DFF   2048
#define BATCH 4
#define LSEQ  2048
#define MTOK  (BATCH * LSEQ)   // 8192 rows
#define NH    8
#define DK    64
#define EPSLN 1e-5f
#define QKVS  1536             // fused qkv row stride

// ---------------------------------------------------------------------------
// Scratch (device globals)
// ---------------------------------------------------------------------------
__device__ __nv_bfloat16 g_hb  [(size_t)MTOK * DM];      // LN outputs (bf16)
__device__ float         g_qkv [(size_t)MTOK * QKVS];    // fused q|k|v (fp32)
__device__ __nv_bfloat16 g_attb[(size_t)MTOK * DM];      // attention out (bf16)
__device__ __nv_bfloat16 g_ffb [(size_t)MTOK * DFF];     // gelu out (bf16)
__device__ __nv_bfloat16 g_wtb [1536*512 + 512*512 + 512*2048 + 512*2048];
__device__ float         g_bqkv[QKVS];

#define WT_O  (1536*512)
#define WT_1  (WT_O + 512*512)
#define WT_2  (WT_1 + 512*2048)

// ---------------------------------------------------------------------------
// PTX helpers (baseline PTX only)
// ---------------------------------------------------------------------------
__device__ __forceinline__ uint32_t smem_u32(const void* p) {
    uint32_t a;
    asm("{ .reg .u64 t; cvta.to.shared.u64 t, %1; cvt.u32.u64 %0, t; }" : "=r"(a) : "l"(p));
    return a;
}
__device__ __forceinline__ float f_rna_tf32(float x) {
    uint32_t u;
    asm("cvt.rna.tf32.f32 %0, %1;" : "=r"(u) : "f"(x));
    return __uint_as_float(u);
}
__device__ __forceinline__ uint32_t pk_bf16(float lo, float hi) {
    __nv_bfloat162 h = __floats2bfloat162_rn(lo, hi);
    return *reinterpret_cast<uint32_t*>(&h);
}

#define CP_ASYNC16(dst, src) \
    asm volatile("cp.async.cg.shared.global [%0], [%1], 16;" :: "r"(dst), "l"(src))
#define CP_COMMIT() asm volatile("cp.async.commit_group;" ::: "memory")
#define CP_WAIT1()  asm volatile("cp.async.wait_group 1;" ::: "memory")

#define LDSM4(r0, r1, r2, r3, addr) \
    asm volatile("ldmatrix.sync.aligned.m8n8.x4.shared.b16 {%0,%1,%2,%3}, [%4];" \
        : "=r"(r0), "=r"(r1), "=r"(r2), "=r"(r3) : "r"(addr))

#define LDSM4T(r0, r1, r2, r3, addr) \
    asm volatile("ldmatrix.sync.aligned.m8n8.x4.trans.shared.b16 {%0,%1,%2,%3}, [%4];" \
        : "=r"(r0), "=r"(r1), "=r"(r2), "=r"(r3) : "r"(addr))

__device__ __forceinline__ void mma_tf32(
    float& d0, float& d1, float& d2, float& d3,
    uint32_t a0, uint32_t a1, uint32_t a2, uint32_t a3,
    uint32_t b0, uint32_t b1)
{
    asm volatile(
        "mma.sync.aligned.m16n8k8.row.col.f32.tf32.tf32.f32 "
        "{%0,%1,%2,%3}, {%4,%5,%6,%7}, {%8,%9}, {%0,%1,%2,%3};"
        : "+f"(d0), "+f"(d1), "+f"(d2), "+f"(d3)
        : "r"(a0), "r"(a1), "r"(a2), "r"(a3), "r"(b0), "r"(b1));
}

__device__ __forceinline__ void mma_bf16(
    float& d0, float& d1, float& d2, float& d3,
    uint32_t a0, uint32_t a1, uint32_t a2, uint32_t a3,
    uint32_t b0, uint32_t b1)
{
    asm volatile(
        "mma.sync.aligned.m16n8k16.row.col.f32.bf16.bf16.f32 "
        "{%0,%1,%2,%3}, {%4,%5,%6,%7}, {%8,%9}, {%0,%1,%2,%3};"
        : "+f"(d0), "+f"(d1), "+f"(d2), "+f"(d3)
        : "r"(a0), "r"(a1), "r"(a2), "r"(a3), "r"(b0), "r"(b1));
}

__device__ __forceinline__ float gelu_exact(float x) {
    return 0.5f * x * (1.0f + erff(x * 0.70710678118654752440f));
}

// exp(x), x<=0, FMA-pipe polynomial (avoids MUFU wall)
__device__ __forceinline__ float exp_fast(float x) {
    float z = x * 1.44269504088896341f;
    z = fmaxf(z, -126.0f);
    float n = floorf(z);
    float f = z - n;
    float p = fmaf(f, 1.54035304e-4f, 0.00133335581f);
    p = fmaf(f, p, 0.00961812911f);
    p = fmaf(f, p, 0.0555041087f);
    p = fmaf(f, p, 0.2402265070f);
    p = fmaf(f, p, 0.69314718056f);
    p = fmaf(f, p, 1.0f);
    return p * __int_as_float(((int)n + 127) << 23);
}

// ---------------------------------------------------------------------------
// LayerNorm body: 2 rows per block, 128 threads/row, float4 path; bf16 out
// ---------------------------------------------------------------------------
__device__ __forceinline__ void ln_body(
    const float* __restrict__ x, const float* __restrict__ g,
    const float* __restrict__ be, __nv_bfloat16* __restrict__ out,
    int rowpair, float red[2][4])
{
    int tid = threadIdx.x;
    int r = tid >> 7;
    int t = tid & 127;
    int wq = (tid >> 5) & 3;
    int row = rowpair * 2 + r;

    float4 v = *reinterpret_cast<const float4*>(x + (size_t)row * DM + t * 4);

    float s = v.x + v.y + v.z + v.w;
    #pragma unroll
    for (int o = 16; o; o >>= 1) s += __shfl_xor_sync(0xffffffffu, s, o);
    if ((tid & 31) == 0) red[r][wq] = s;
    __syncthreads();
    float mu = (red[r][0] + red[r][1] + red[r][2] + red[r][3]) * (1.0f / DM);
    __syncthreads();

    float4 d;
    d.x = v.x - mu; d.y = v.y - mu; d.z = v.z - mu; d.w = v.w - mu;
    s = d.x * d.x + d.y * d.y + d.z * d.z + d.w * d.w;
    #pragma unroll
    for (int o = 16; o; o >>= 1) s += __shfl_xor_sync(0xffffffffu, s, o);
    if ((tid & 31) == 0) red[r][wq] = s;
    __syncthreads();
    float rs = rsqrtf((red[r][0] + red[r][1] + red[r][2] + red[r][3]) * (1.0f / DM)
                      + EPSLN);

    float4 gv = *reinterpret_cast<const float4*>(g + t * 4);
    float4 bv = *reinterpret_cast<const float4*>(be + t * 4);
    uint2 o2;
    o2.x = pk_bf16(d.x * rs * gv.x + bv.x, d.y * rs * gv.y + bv.y);
    o2.y = pk_bf16(d.z * rs * gv.z + bv.z, d.w * rs * gv.w + bv.w);
    *reinterpret_cast<uint2*>(out + (size_t)row * DM + t * 4) = o2;
}

__global__ __launch_bounds__(256) void layernorm_kernel(
    const float* __restrict__ x, const float* __restrict__ g,
    const float* __restrict__ be, __nv_bfloat16* __restrict__ out)
{
    __shared__ float red[2][4];
    ln_body(x, g, be, out, blockIdx.x, red);
}

// ---------------------------------------------------------------------------
// Prologue mega-kernel: 6 weight transposes + bias concat + LN1, one launch.
// bid < 3072: transpose 32x32 tile; bid < 3078: bias concat; else LN1 rows.
// ---------------------------------------------------------------------------
__global__ __launch_bounds__(256) void prep_kernel(
    const float* __restrict__ Wq, const float* __restrict__ Wk,
    const float* __restrict__ Wv, const float* __restrict__ Wo,
    const float* __restrict__ W1, const float* __restrict__ W2,
    __nv_bfloat16* __restrict__ wtb,
    const float* __restrict__ bq, const float* __restrict__ bk,
    const float* __restrict__ bv, float* __restrict__ bqkv,
    const float* __restrict__ x, const float* __restrict__ g1,
    const float* __restrict__ be1, __nv_bfloat16* __restrict__ hb)
{
    __shared__ float t[32][33];
    int bid = blockIdx.x;
    int tid = threadIdx.x;

    if (bid < 3072) {
        const float* in;
        __nv_bfloat16* out;
        int R, C, lb;
        if (bid < 256)        { in = Wq; out = wtb;              R = 512;  C = 512;  lb = bid; }
        else if (bid < 512)   { in = Wk; out = wtb + 512 * 512;  R = 512;  C = 512;  lb = bid - 256; }
        else if (bid < 768)   { in = Wv; out = wtb + 1024 * 512; R = 512;  C = 512;  lb = bid - 512; }
        else if (bid < 1024)  { in = Wo; out = wtb + WT_O;       R = 512;  C = 512;  lb = bid - 768; }
        else if (bid < 2048)  { in = W1; out = wtb + WT_1;       R = 512;  C = 2048; lb = bid - 1024; }
        else                  { in = W2; out = wtb + WT_2;       R = 2048; C = 512;  lb = bid - 2048; }
        int nbx = C >> 5;
        int bx = (lb % nbx) << 5;
        int by = (lb / nbx) << 5;
        int txl = tid & 31, tyl = tid >> 5;
        #pragma unroll
        for (int i = 0; i < 32; i += 8)
            t[tyl + i][txl] = in[(size_t)(by + tyl + i) * C + bx + txl];
        __syncthreads();
        #pragma unroll
        for (int i = 0; i < 32; i += 8)
            out[(size_t)(bx + tyl + i) * R + by + txl] =
                __float2bfloat16_rn(t[txl][tyl + i]);
    } else if (bid < 3078) {
        int i = (bid - 3072) * 256 + tid;
        if (i < QKVS)
            bqkv[i] = i < 512 ? bq[i] : (i < 1024 ? bk[i - 512] : bv[i - 1024]);
    } else {
        ln_body(x, g1, be1, hb, bid - 3078, t[0]
                ? (float(*)[4])t : (float(*)[4])t);   // reuse shared
    }
}

// ---------------------------------------------------------------------------
// bf16 tensor-core GEMM (R13 config — frozen best).
//   mode 0: bias, fp32 out; 1: bias+GELU, bf16 out; 2: bias+residual, fp32.
// CTA tile 128x128, K-chunk 64, 2-stage cp.async, 256 thr, occupancy 2.
// ---------------------------------------------------------------------------
#define GP    36                  // smem row pitch in u32 (= 72 bf16, 144B)
#define OSTG  (128 * GP)          // per operand per stage (u32)
#define STG   (2 * OSTG)          // per stage (u32)
#define SMEM_GEMM (2 * STG * 4)   // 73728 bytes

__global__ __launch_bounds__(256, 2) void gemm_bf16_kernel(
    const __nv_bfloat16* __restrict__ A, const __nv_bfloat16* __restrict__ BT,
    const float* __restrict__ bias, const float* __restrict__ res,
    void* __restrict__ Cv, int M, int N, int K, int mode)
{
    extern __shared__ float smem[];
    const uint32_t sb = smem_u32(smem);
    const int tid = threadIdx.x;
    const int wid = tid >> 5;
    const int lid = tid & 31;
    const int g = lid >> 2;
    const int t = lid & 3;
    const int bm = blockIdx.y * 128;
    const int bn = blockIdx.x * 128;
    const int m_off = (wid & 1) * 64;
    const int n_off = (wid >> 1) * 32;
    const int nchunk = K >> 6;

    const int lr  = lid & 7;
    const int lt3 = lid >> 3;
    const uint32_t aRow  = m_off + (lt3 & 1) * 8 + lr;
    const uint32_t aKoff = (uint32_t)(lt3 >> 1) * 4;
    const uint32_t bRow  = n_off + (lt3 >> 1) * 8 + lr;
    const uint32_t bKoff = (uint32_t)(lt3 & 1) * 4;

    float acc[4][4][4];
    #pragma unroll
    for (int mf = 0; mf < 4; mf++)
        #pragma unroll
        for (int nf = 0; nf < 4; nf++)
            #pragma unroll
            for (int r = 0; r < 4; r++) acc[mf][nf][r] = 0.f;

    auto issue = [&](int c, int s) {
        const int k0 = c << 6;
        const uint32_t sbase = sb + (uint32_t)(s * STG) * 4u;
        #pragma unroll
        for (int it = 0; it < 8; it++) {
            int u = it * 256 + tid;
            int op = u >> 10;
            int v = u & 1023;
            int row = v >> 3;
            int c8 = v & 7;
            const __nv_bfloat16* src = op
                ? (BT + (size_t)(bn + row) * K + k0 + (c8 << 3))
                : (A  + (size_t)(bm + row) * K + k0 + (c8 << 3));
            uint32_t dst = sbase +
                (uint32_t)(op * OSTG + row * GP + (c8 << 2)) * 4u;
            CP_ASYNC16(dst, src);
        }
    };

    issue(0, 0);
    CP_COMMIT();

    int buf = 0;
    for (int c = 0; c < nchunk; c++) {
        if (c + 1 < nchunk) issue(c + 1, buf ^ 1);
        CP_COMMIT();
        CP_WAIT1();
        __syncthreads();

        const uint32_t sA = sb + (uint32_t)(buf * STG) * 4u;
        const uint32_t sB = sA + (uint32_t)OSTG * 4u;

        #pragma unroll
        for (int ks = 0; ks < 4; ks++) {
            const uint32_t kb = ks * 8;
            uint32_t b01[4], b23[4];
            LDSM4(b01[0], b01[1], b01[2], b01[3],
                  sB + ((bRow +  0) * GP + kb + bKoff) * 4u);
            LDSM4(b23[0], b23[1], b23[2], b23[3],
                  sB + ((bRow + 16) * GP + kb + bKoff) * 4u);
            uint32_t aC[4], aN[4];
            LDSM4(aC[0], aC[1], aC[2], aC[3],
                  sA + ((aRow + 0 * 16) * GP + kb + aKoff) * 4u);
            #pragma unroll
            for (int mf = 0; mf < 4; mf++) {
                if (mf < 3)
                    LDSM4(aN[0], aN[1], aN[2], aN[3],
                          sA + ((aRow + (mf + 1) * 16) * GP + kb + aKoff) * 4u);
                mma_bf16(acc[mf][0][0], acc[mf][0][1], acc[mf][0][2], acc[mf][0][3],
                         aC[0], aC[1], aC[2], aC[3], b01[0], b01[1]);
                mma_bf16(acc[mf][1][0], acc[mf][1][1], acc[mf][1][2], acc[mf][1][3],
                         aC[0], aC[1], aC[2], aC[3], b01[2], b01[3]);
                mma_bf16(acc[mf][2][0], acc[mf][2][1], acc[mf][2][2], acc[mf][2][3],
                         aC[0], aC[1], aC[2], aC[3], b23[0], b23[1]);
                mma_bf16(acc[mf][3][0], acc[mf][3][1], acc[mf][3][2], acc[mf][3][3],
                         aC[0], aC[1], aC[2], aC[3], b23[2], b23[3]);
                #pragma unroll
                for (int r = 0; r < 4; r++) aC[r] = aN[r];
            }
        }
        __syncthreads();
        buf ^= 1;
    }

    // ---- epilogue ----
    #pragma unroll
    for (int nf = 0; nf < 4; nf++) {
        int col = bn + n_off + nf * 8 + 2 * t;
        float2 bi = *reinterpret_cast<const float2*>(bias + col);
        #pragma unroll
        for (int mf = 0; mf < 4; mf++) {
            int r0 = bm + m_off + mf * 16 + g;
            #pragma unroll
            for (int half = 0; half < 2; half++) {
                int r = r0 + half * 8;
                float v0 = acc[mf][nf][half * 2 + 0] + bi.x;
                float v1 = acc[mf][nf][half * 2 + 1] + bi.y;
                if (mode == 1) {
                    __nv_bfloat162 o2 = __floats2bfloat162_rn(
                        gelu_exact(v0), gelu_exact(v1));
                    *reinterpret_cast<__nv_bfloat162*>(
                        (__nv_bfloat16*)Cv + (size_t)r * N + col) = o2;
                } else {
                    if (mode == 2) {
                        float2 rv = *reinterpret_cast<const float2*>(
                            res + (size_t)r * N + col);
                        v0 += rv.x; v1 += rv.y;
                    }
                    float2 o; o.x = v0; o.y = v1;
                    *reinterpret_cast<float2*>(
                        (float*)Cv + (size_t)r * N + col) = o;
                }
            }
        }
    }
}

// ---------------------------------------------------------------------------
// Tensor-core causal flash attention (R13 version — frozen best).
// QK^T tf32 via ldmatrix; V bf16 once + trans-ldmatrix PV; P register-direct.
// CTA = 128 queries x (b,h); 8 warps x 16 rows; occupancy 2 (~62KB smem).
// ---------------------------------------------------------------------------
#define QS_PAD 68
#define KS_PAD 76
#define VBP    72                              // V bf16 pitch (bf16 units)
#define QS_OFF 0
#define KS_OFF (128 * QS_PAD)                  // 8704 (floats)
#define MK_OFF (KS_OFF + 64 * KS_PAD)          // 13568
#define VB_OFF (MK_OFF + 64)                   // 13632 (float units)
#define SMEM_ATTN ((VB_OFF * 4) + 64 * VBP * 2) // 63744 bytes

__global__ __launch_bounds__(256, 2) void attn_tc_kernel(
    const float* __restrict__ QKV, const int* __restrict__ mask,
    __nv_bfloat16* __restrict__ O)
{
    extern __shared__ float sm[];
    float* Qs = sm + QS_OFF;
    float* Ks = sm + KS_OFF;
    int*   mk = (int*)(sm + MK_OFF);
    const uint32_t sb = smem_u32(sm);
    const uint32_t sKs = sb + (uint32_t)KS_OFF * 4u;
    const uint32_t sVb = sb + (uint32_t)VB_OFF * 4u;

    const int qt = (int)gridDim.x - 1 - (int)blockIdx.x;
    const int h = blockIdx.y, b = blockIdx.z;
    const int q0 = qt * 128;
    const int tid = threadIdx.x;
    const int w = tid >> 5;
    const int lid = tid & 31;
    const int g = lid >> 2;
    const int t = lid & 3;
    const size_t baseQ = (size_t)b * LSEQ * QKVS + (size_t)h * DK;
    const size_t baseK = baseQ + DM;
    const size_t baseV = baseQ + 2 * DM;
    const size_t baseO = (size_t)b * LSEQ * DM + (size_t)h * DK;

    const int lr  = lid & 7;
    const int sub = lid >> 3;
    const uint32_t qOff = (uint32_t)(lid & 15) * QS_PAD + (uint32_t)(lid >> 4) * 4;
    const uint32_t kOff = ((uint32_t)lr + (uint32_t)(sub & 2) * 4) * KS_PAD
                        + (uint32_t)(sub & 1) * 4;
    const uint32_t vRowOff = (uint32_t)((sub & 1) * 8 + lr) * VBP;
    const uint32_t vColOff = (uint32_t)(sub >> 1) * 8;

    #pragma unroll
    for (int it = 0; it < 8; it++) {
        int li = it * 256 + tid;
        int r = li >> 4;
        int c = (li & 15) << 2;
        float4 v = *reinterpret_cast<const float4*>(
            QKV + baseQ + (size_t)(q0 + r) * QKVS + c);
        float* d = Qs + r * QS_PAD + c;
        d[0] = f_rna_tf32(v.x); d[1] = f_rna_tf32(v.y);
        d[2] = f_rna_tf32(v.z); d[3] = f_rna_tf32(v.w);
    }
    __syncthreads();

    float acc[8][4];
    #pragma unroll
    for (int nf = 0; nf < 8; nf++)
        #pragma unroll
        for (int r = 0; r < 4; r++) acc[nf][r] = 0.f;
    float m_lo = -1e30f, m_hi = -1e30f, l_lo = 0.f, l_hi = 0.f;

    const int row_lo = q0 + w * 16 + g;
    const int row_hi = row_lo + 8;
    const uint32_t sQw = sb + (uint32_t)(w * 16 * QS_PAD) * 4u;
    const int nkb = 2 * qt + 2;

    for (int kb = 0; kb < nkb; kb++) {
        const int k0 = kb * 64;

        #pragma unroll
        for (int it = 0; it < 4; it++) {
            int li = it * 256 + tid;
            int r = li >> 4;
            int c = (li & 15) << 2;
            float4 kv = *reinterpret_cast<const float4*>(
                QKV + baseK + (size_t)(k0 + r) * QKVS + c);
            float4 vv = *reinterpret_cast<const float4*>(
                QKV + baseV + (size_t)(k0 + r) * QKVS + c);
            float* dk = Ks + r * KS_PAD + c;
            dk[0] = f_rna_tf32(kv.x); dk[1] = f_rna_tf32(kv.y);
            dk[2] = f_rna_tf32(kv.z); dk[3] = f_rna_tf32(kv.w);
            uint32_t p0 = pk_bf16(vv.x, vv.y);
            uint32_t p1 = pk_bf16(vv.z, vv.w);
            asm volatile("st.shared.v2.b32 [%0], {%1,%2};"
                :: "r"(sVb + (uint32_t)(r * VBP + c) * 2u),
                   "r"(p0), "r"(p1) : "memory");
        }
        if (tid < 64) mk[tid] = mask[b * LSEQ + k0 + tid];
        __syncthreads();

        float s[8][4];
        #pragma unroll
        for (int nf = 0; nf < 8; nf++)
            #pragma unroll
            for (int r = 0; r < 4; r++) s[nf][r] = 0.f;

        #pragma unroll
        for (int ks = 0; ks < 8; ks++) {
            const uint32_t ko = ks * 8;
            uint32_t qa0, qa1, qa2, qa3;
            LDSM4(qa0, qa1, qa2, qa3, sQw + (qOff + ko) * 4u);
            #pragma unroll
            for (int np = 0; np < 4; np++) {
                uint32_t k0r, k1r, k2r, k3r;
                LDSM4(k0r, k1r, k2r, k3r,
                      sKs + ((uint32_t)(np * 16) * KS_PAD + kOff + ko) * 4u);
                mma_tf32(s[2*np  ][0], s[2*np  ][1], s[2*np  ][2], s[2*np  ][3],
                         qa0, qa1, qa2, qa3, k0r, k1r);
                mma_tf32(s[2*np+1][0], s[2*np+1][1], s[2*np+1][2], s[2*np+1][3],
                         qa0, qa1, qa2, qa3, k2r, k3r);
            }
        }

        #pragma unroll
        for (int nf = 0; nf < 8; nf++) {
            int cl = nf * 8 + 2 * t;
            int key0 = k0 + cl;
            int key1 = key0 + 1;
            int m0 = mk[cl];
            int m1 = mk[cl + 1];
            s[nf][0] = (key0 > row_lo || m0 == 0) ? -1e9f : s[nf][0] * 0.125f;
            s[nf][1] = (key1 > row_lo || m1 == 0) ? -1e9f : s[nf][1] * 0.125f;
            s[nf][2] = (key0 > row_hi || m0 == 0) ? -1e9f : s[nf][2] * 0.125f;
            s[nf][3] = (key1 > row_hi || m1 == 0) ? -1e9f : s[nf][3] * 0.125f;
        }

        float bm_lo = s[0][0], bm_hi = s[0][2];
        #pragma unroll
        for (int nf = 0; nf < 8; nf++) {
            bm_lo = fmaxf(bm_lo, fmaxf(s[nf][0], s[nf][1]));
            bm_hi = fmaxf(bm_hi, fmaxf(s[nf][2], s[nf][3]));
        }
        bm_lo = fmaxf(bm_lo, __shfl_xor_sync(0xffffffffu, bm_lo, 1));
        bm_lo = fmaxf(bm_lo, __shfl_xor_sync(0xffffffffu, bm_lo, 2));
        bm_hi = fmaxf(bm_hi, __shfl_xor_sync(0xffffffffu, bm_hi, 1));
        bm_hi = fmaxf(bm_hi, __shfl_xor_sync(0xffffffffu, bm_hi, 2));

        float mn_lo = fmaxf(m_lo, bm_lo);
        float mn_hi = fmaxf(m_hi, bm_hi);
        float co_lo = exp_fast(m_lo - mn_lo);
        float co_hi = exp_fast(m_hi - mn_hi);

        float sum_lo = 0.f, sum_hi = 0.f;
        #pragma unroll
        for (int nf = 0; nf < 8; nf++) {
            s[nf][0] = exp_fast(s[nf][0] - mn_lo);
            s[nf][1] = exp_fast(s[nf][1] - mn_lo);
            s[nf][2] = exp_fast(s[nf][2] - mn_hi);
            s[nf][3] = exp_fast(s[nf][3] - mn_hi);
            sum_lo += s[nf][0] + s[nf][1];
            sum_hi += s[nf][2] + s[nf][3];
        }
        sum_lo += __shfl_xor_sync(0xffffffffu, sum_lo, 1);
        sum_lo += __shfl_xor_sync(0xffffffffu, sum_lo, 2);
        sum_hi += __shfl_xor_sync(0xffffffffu, sum_hi, 1);
        sum_hi += __shfl_xor_sync(0xffffffffu, sum_hi, 2);

        l_lo = l_lo * co_lo + sum_lo;
        l_hi = l_hi * co_hi + sum_hi;
        m_lo = mn_lo; m_hi = mn_hi;
        #pragma unroll
        for (int nf = 0; nf < 8; nf++) {
            acc[nf][0] *= co_lo; acc[nf][1] *= co_lo;
            acc[nf][2] *= co_hi; acc[nf][3] *= co_hi;
        }

        #pragma unroll
        for (int ks = 0; ks < 4; ks++) {
            uint32_t a0 = pk_bf16(s[2 * ks    ][0], s[2 * ks    ][1]);
            uint32_t a1 = pk_bf16(s[2 * ks    ][2], s[2 * ks    ][3]);
            uint32_t a2 = pk_bf16(s[2 * ks + 1][0], s[2 * ks + 1][1]);
            uint32_t a3 = pk_bf16(s[2 * ks + 1][2], s[2 * ks + 1][3]);
            const uint32_t vk = (uint32_t)(ks * 16) * VBP;
            #pragma unroll
            for (int np = 0; np < 4; np++) {
                uint32_t b0, b1, b2, b3;
                LDSM4T(b0, b1, b2, b3,
                       sVb + (vk + vRowOff + (uint32_t)(np * 16) + vColOff) * 2u);
                mma_bf16(acc[2*np  ][0], acc[2*np  ][1], acc[2*np  ][2], acc[2*np  ][3],
                         a0, a1, a2, a3, b0, b1);
                mma_bf16(acc[2*np+1][0], acc[2*np+1][1], acc[2*np+1][2], acc[2*np+1][3],
                         a0, a1, a2, a3, b2, b3);
            }
        }
        __syncthreads();
    }

    float inv_lo = 1.0f / l_lo;
    float inv_hi = 1.0f / l_hi;
    #pragma unroll
    for (int nf = 0; nf < 8; nf++) {
        int cl = nf * 8 + 2 * t;
        __nv_bfloat162 o2;
        o2 = __floats2bfloat162_rn(acc[nf][0] * inv_lo, acc[nf][1] * inv_lo);
        *reinterpret_cast<__nv_bfloat162*>(
            O + baseO + (size_t)row_lo * DM + cl) = o2;
        o2 = __floats2bfloat162_rn(acc[nf][2] * inv_hi, acc[nf][3] * inv_hi);
        *reinterpret_cast<__nv_bfloat162*>(
            O + baseO + (size_t)row_hi * DM + cl) = o2;
    }
}

// ---------------------------------------------------------------------------
// Launch
// ---------------------------------------------------------------------------
extern "C" void kernel_launch(void* const* d_in, const int* in_sizes, int n_in,
                              void* d_out, int out_size)
{
    const float* x    = (const float*)d_in[0];
    const int*   mask = (const int*)  d_in[1];
    const float* Wq   = (const float*)d_in[2];
    const float* bq   = (const float*)d_in[3];
    const float* Wk   = (const float*)d_in[4];
    const float* bk   = (const float*)d_in[5];
    const float* Wv   = (const float*)d_in[6];
    const float* bv   = (const float*)d_in[7];
    const float* Wo   = (const float*)d_in[8];
    const float* bo   = (const float*)d_in[9];
    const float* g1   = (const float*)d_in[10];
    const float* be1  = (const float*)d_in[11];
    const float* g2   = (const float*)d_in[12];
    const float* be2  = (const float*)d_in[13];
    const float* W1   = (const float*)d_in[14];
    const float* b1   = (const float*)d_in[15];
    const float* W2   = (const float*)d_in[16];
    const float* b2   = (const float*)d_in[17];
    float* out = (float*)d_out;

    __nv_bfloat16 *hb, *attb, *ffb, *wtb;
    float *qkv, *bqkv;
    cudaGetSymbolAddress((void**)&hb,   g_hb);
    cudaGetSymbolAddress((void**)&qkv,  g_qkv);
    cudaGetSymbolAddress((void**)&attb, g_attb);
    cudaGetSymbolAddress((void**)&ffb,  g_ffb);
    cudaGetSymbolAddress((void**)&wtb,  g_wtb);
    cudaGetSymbolAddress((void**)&bqkv, g_bqkv);

    cudaFuncSetAttribute(gemm_bf16_kernel,
        cudaFuncAttributeMaxDynamicSharedMemorySize, SMEM_GEMM);
    cudaFuncSetAttribute(attn_tc_kernel,
        cudaFuncAttributeMaxDynamicSharedMemorySize, SMEM_ATTN);

    // 0. transposes + bias concat + LN1 in ONE launch
    prep_kernel<<<3078 + MTOK / 2, 256>>>(
        Wq, Wk, Wv, Wo, W1, W2, wtb, bq, bk, bv, bqkv, x, g1, be1, hb);

    // 1. fused QKV projection -> qkv [M][1536] (fp32)
    gemm_bf16_kernel<<<dim3(QKVS / 128, MTOK / 128), 256, SMEM_GEMM>>>(
        hb, wtb, bqkv, nullptr, qkv, MTOK, QKVS, DM, 0);

    // 2. causal attention -> attb (bf16)
    dim3 gattn(LSEQ / 128, NH, BATCH);
    attn_tc_kernel<<<gattn, 256, SMEM_ATTN>>>(qkv, mask, attb);

    // 3. O projection + residual(x) -> out
    gemm_bf16_kernel<<<dim3(DM / 128, MTOK / 128), 256, SMEM_GEMM>>>(
        attb, wtb + WT_O, bo, x, out, MTOK, DM, DM, 2);

    // 4. ln2(out) -> hb
    layernorm_kernel<<<MTOK / 2, 256>>>(out, g2, be2, hb);

    // 5. FFN1 + GELU -> ffb (bf16)
    gemm_bf16_kernel<<<dim3(DFF / 128, MTOK / 128), 256, SMEM_GEMM>>>(
        hb, wtb + WT_1, b1, nullptr, ffb, MTOK, DFF, DM, 1);

    // 6. FFN2 + residual -> out
    gemm_bf16_kernel<<<dim3(DM / 128, MTOK / 128), 256, SMEM_GEMM>>>(
        ffb, wtb + WT_2, b2, out, out, MTOK, DM, DFF, 2);
}